// round 17
// baseline (speedup 1.0000x reference)
#include <cuda_runtime.h>
#include <cuda_bf16.h>
#include <math.h>
#include <cstdint>

#define Bv 2
#define Tv 2048
#define NXv 512
#define HDv 128
#define Lv 64
#define KIv 32
#define NN (NXv*NXv)

// ================= scratch (device globals; no allocation allowed) =================
__device__ float g_v[Bv*Tv*NXv];
__device__ float g_w1 [Bv*4*Tv*Lv];
__device__ float g_w2t[Bv*4*Tv*Lv];
__device__ int   g_cols[Bv*Tv*KIv];
__device__ int   g_cnt [Bv*Tv];
__device__ float g_vpart[8*Bv*NXv];
__device__ float g_scal[2];
__device__ __nv_bfloat16 g_xh[Bv*Tv*NXv], g_xl[Bv*Tv*NXv];
__device__ __nv_bfloat16 g_ah[Bv*Tv*NXv], g_al[Bv*Tv*NXv];
__device__ __nv_bfloat16 g_wh[2*NN], g_wl[2*NN];          // wv (slot 0), wo (slot 1)
__device__ __nv_bfloat16 g_wqth[NN], g_wqtl[NN];          // wq transposed splits
__device__ __nv_bfloat16 g_wkth[NN], g_wktl[NN];          // wk transposed splits
__device__ float g_xlm[128*NXv];                          // gathered landmark x rows (fp32)
__device__ float g_qlm[128*384], g_klm[128*384];          // landmark q/k (fp32, heads 1-3)
__device__ __nv_bfloat16 g_skh[Bv*3*Lv*HDv], g_skl[Bv*3*Lv*HDv];
__device__ __nv_bfloat16 g_sqh[Bv*3*Lv*HDv], g_sql[Bv*3*Lv*HDv];
__device__ __nv_bfloat16 g_mh[Bv*3*128*NXv], g_ml[Bv*3*128*NXv];  // [bh][M1;M2][512]

// ================= helpers =================
__device__ __forceinline__ uint32_t smem_u32(const void* p) {
    uint32_t a;
    asm("{ .reg .u64 t; cvta.to.shared.u64 t, %1; cvt.u32.u64 %0, t; }" : "=r"(a) : "l"(p));
    return a;
}
__device__ __forceinline__ uint32_t sw128(uint32_t off) { return off ^ ((off >> 3) & 0x70); }

#define CP16(dst, src)  asm volatile("cp.async.cg.shared.global [%0], [%1], 16;" :: "r"(dst), "l"(src) : "memory")
#define CP_COMMIT()     asm volatile("cp.async.commit_group;" ::: "memory")

#define LDSM4(r, a) \
    asm volatile("ldmatrix.sync.aligned.m8n8.x4.shared.b16 {%0,%1,%2,%3}, [%4];" \
        : "=r"((r)[0]), "=r"((r)[1]), "=r"((r)[2]), "=r"((r)[3]) : "r"(a))

#define MMA16816(d, a, b) \
    asm volatile("mma.sync.aligned.m16n8k16.row.col.f32.bf16.bf16.f32 " \
        "{%0,%1,%2,%3},{%4,%5,%6,%7},{%8,%9},{%0,%1,%2,%3};" \
        : "+f"((d)[0]), "+f"((d)[1]), "+f"((d)[2]), "+f"((d)[3]) \
        : "r"((a)[0]), "r"((a)[1]), "r"((a)[2]), "r"((a)[3]), "r"((b)[0]), "r"((b)[1]))

// ====== generalized split-bf16 MMA mainloop: C[64,128] tile, K = nchunks*64 ========
// Stage: A 2x8KB (64 rows x 64 elems, hi/lo) + B 2x16KB (128 rows x 64) = 48KB, 2 stages.
#define STAGE_BYTES 49152
#define GEMM_SMEM_TOTAL (2*STAGE_BYTES)

__device__ __forceinline__ void mainloop_gen(
    const __nv_bfloat16* __restrict__ Ah, const __nv_bfloat16* __restrict__ Al, int lda,
    const __nv_bfloat16* __restrict__ Bh, const __nv_bfloat16* __restrict__ Bl, int ldb,
    int m0, int nchunks, char* smem, float acc[2][4][4])
{
    const uint32_t sb = smem_u32(smem);
    const int tid = threadIdx.x, lane = tid & 31;
    const int wid = tid >> 5;
    const int wm = wid & 1, wn = wid >> 1;

    auto load_stage = [&](int kc, uint32_t dstb) {
#pragma unroll
        for (int t = 0; t < 2; ++t) {
            const __nv_bfloat16* base = t ? Al : Ah;
#pragma unroll
            for (int j = 0; j < 2; ++j) {
                int idx = j * 256 + tid;
                int row = idx >> 3, c = idx & 7;
                CP16(dstb + t * 8192 + sw128((uint32_t)(row * 128 + c * 16)),
                     base + (size_t)(m0 + row) * lda + kc * 64 + c * 8);
            }
        }
#pragma unroll
        for (int t = 0; t < 2; ++t) {
            const __nv_bfloat16* base = t ? Bl : Bh;
#pragma unroll
            for (int j = 0; j < 4; ++j) {
                int idx = j * 256 + tid;
                int row = idx >> 3, c = idx & 7;
                CP16(dstb + 16384 + t * 16384 + sw128((uint32_t)(row * 128 + c * 16)),
                     base + (size_t)row * ldb + kc * 64 + c * 8);
            }
        }
    };

    load_stage(0, sb);
    CP_COMMIT();

    for (int kc = 0; kc < nchunks; ++kc) {
        if (kc < nchunks - 1) {
            load_stage(kc + 1, sb + ((kc + 1) & 1) * STAGE_BYTES);
            CP_COMMIT();
            asm volatile("cp.async.wait_group 1;" ::: "memory");
        } else {
            asm volatile("cp.async.wait_group 0;" ::: "memory");
        }
        __syncthreads();
        const uint32_t sbuf = sb + (kc & 1) * STAGE_BYTES;

#pragma unroll
        for (int kk = 0; kk < 4; ++kk) {
            const int klo = kk * 2;
            uint32_t ah[2][4], al[2][4], bh[4][2], bl[4][2];
            const int arow = ((lane >> 3) & 1) * 8 + (lane & 7);
            const int achk = klo + (lane >> 4);
#pragma unroll
            for (int f = 0; f < 2; ++f) {
                uint32_t off = sw128((uint32_t)((wm * 32 + f * 16 + arow) * 128 + achk * 16));
                LDSM4(ah[f], sbuf + off);
                LDSM4(al[f], sbuf + 8192 + off);
            }
            const int brow = (lane >> 4) * 8 + (lane & 7);
            const int bchk = klo + ((lane >> 3) & 1);
#pragma unroll
            for (int p = 0; p < 2; ++p) {
                uint32_t off = sw128((uint32_t)((wn * 32 + p * 16 + brow) * 128 + bchk * 16));
                uint32_t r[4];
                LDSM4(r, sbuf + 16384 + off);
                bh[2*p][0] = r[0]; bh[2*p][1] = r[1];
                bh[2*p+1][0] = r[2]; bh[2*p+1][1] = r[3];
                LDSM4(r, sbuf + 32768 + off);
                bl[2*p][0] = r[0]; bl[2*p][1] = r[1];
                bl[2*p+1][0] = r[2]; bl[2*p+1][1] = r[3];
            }
#pragma unroll
            for (int f = 0; f < 2; ++f)
#pragma unroll
                for (int n = 0; n < 4; ++n) {
                    MMA16816(acc[f][n], ah[f], bh[n]);
                    MMA16816(acc[f][n], ah[f], bl[n]);
                    MMA16816(acc[f][n], al[f], bh[n]);
                }
        }
        __syncthreads();
    }
}

// v projection. grid (64, 4): slabs 0..3 -> fp32 g_v. wv = g_wh slot 0.
__global__ void __launch_bounds__(256, 2) gemm_v()
{
    extern __shared__ char smem[];
    const int slab = blockIdx.y * 128;
    const int m0 = blockIdx.x * 64;

    float acc[2][4][4] = {};
    mainloop_gen(g_xh, g_xl, 512,
                 g_wh + (size_t)slab * 512, g_wl + (size_t)slab * 512, 512,
                 m0, 8, smem, acc);

    const int tid = threadIdx.x, lane = tid & 31;
    const int wid = tid >> 5;
    const int wm = wid & 1, wn = wid >> 1;
    const int r0 = m0 + wm * 32 + (lane >> 2);
    const int c0 = slab + wn * 32 + (lane & 3) * 2;
#pragma unroll
    for (int f = 0; f < 2; ++f)
#pragma unroll
        for (int n = 0; n < 4; ++n) {
            float* p0 = g_v + (size_t)(r0 + f * 16) * 512 + c0 + n * 8;
            *(float2*)p0 = make_float2(acc[f][n][0], acc[f][n][1]);
            *(float2*)(p0 + 8 * 512) = make_float2(acc[f][n][2], acc[f][n][3]);
        }
}

// Output projection: out = a @ wo^T (wo = g_wh slot 1). grid (32, 4), window m_base.
__global__ void __launch_bounds__(256, 2) gemm_out(float* __restrict__ out, int m_base)
{
    extern __shared__ char smem[];
    const int brow = blockIdx.y * 128;
    const int m0 = m_base + blockIdx.x * 64;
    float acc[2][4][4] = {};
    mainloop_gen(g_ah, g_al, 512,
                 g_wh + NN + (size_t)brow * 512, g_wl + NN + (size_t)brow * 512, 512,
                 m0, 8, smem, acc);
    const int tid = threadIdx.x, lane = tid & 31;
    const int wid = tid >> 5;
    const int wm = wid & 1, wn = wid >> 1;
    const int r0 = m0 + wm * 32 + (lane >> 2);
    const int c0 = brow + wn * 32 + (lane & 3) * 2;
#pragma unroll
    for (int f = 0; f < 2; ++f)
#pragma unroll
        for (int n = 0; n < 4; ++n) {
            float* p0 = out + (size_t)(r0 + f * 16) * 512 + c0 + n * 8;
            *(float2*)p0 = make_float2(acc[f][n][0], acc[f][n][1]);
            *(float2*)(p0 + 8 * 512) = make_float2(acc[f][n][2], acc[f][n][3]);
        }
}

// M-gemm: M1[j,e] = sum_d sk[j,d]*wqT[e, h*128+d]; M2 uses (sq, wkT).
// grid (4 e-tiles, 6 bh, 2 which). K=128 (2 chunks). Writes split bf16 into g_mh/g_ml:
// rows [bh*128 + which*64 + j], cols e.
__global__ void __launch_bounds__(256, 2) mgemm()
{
    extern __shared__ char smem[];
    const int which = blockIdx.z;
    const int bh = blockIdx.y;
    const int hm = bh % 3;
    const int e0 = blockIdx.x * 128;

    const __nv_bfloat16* Ah = (which ? g_sqh : g_skh) + (size_t)bh * 64 * 128;
    const __nv_bfloat16* Al = (which ? g_sql : g_skl) + (size_t)bh * 64 * 128;
    const __nv_bfloat16* Bh = (which ? g_wkth : g_wqth) + (size_t)e0 * 512 + (hm + 1) * 128;
    const __nv_bfloat16* Bl = (which ? g_wktl : g_wqtl) + (size_t)e0 * 512 + (hm + 1) * 128;

    float acc[2][4][4] = {};
    mainloop_gen(Ah, Al, 128, Bh, Bl, 512, 0, 2, smem, acc);

    const int tid = threadIdx.x, lane = tid & 31;
    const int wid = tid >> 5;
    const int wm = wid & 1, wn = wid >> 1;
    const int j0 = wm * 32 + (lane >> 2);
    const int cc = wn * 32 + (lane & 3) * 2;
    const size_t rowbase = (size_t)bh * 128 + which * 64;
#pragma unroll
    for (int f = 0; f < 2; ++f)
#pragma unroll
        for (int n = 0; n < 4; ++n) {
#pragma unroll
            for (int hr = 0; hr < 2; ++hr) {
                const int j = j0 + f * 16 + hr * 8;
                float v0 = acc[f][n][hr*2], v1 = acc[f][n][hr*2+1];
                __nv_bfloat16 h0 = __float2bfloat16(v0), h1 = __float2bfloat16(v1);
                size_t o = (rowbase + j) * 512 + e0 + cc + n * 8;
                *(__nv_bfloat162*)(g_mh + o) = __halves2bfloat162(h0, h1);
                *(__nv_bfloat162*)(g_ml + o) = __halves2bfloat162(
                    __float2bfloat16(v0 - __bfloat162float(h0)),
                    __float2bfloat16(v1 - __bfloat162float(h1)));
            }
        }
}

// w-gemm: [w1|w2t][b,hm] = x_b @ [M1;M2]^T. grid (32 t-tiles, 3 hm, 2 b). N=128.
__global__ void __launch_bounds__(256, 2) wgemm()
{
    extern __shared__ char smem[];
    const int hm = blockIdx.y, b = blockIdx.z;
    const int m0 = blockIdx.x * 64;

    float acc[2][4][4] = {};
    mainloop_gen(g_xh + (size_t)b * Tv * 512, g_xl + (size_t)b * Tv * 512, 512,
                 g_mh + (size_t)(b*3 + hm) * 128 * 512,
                 g_ml + (size_t)(b*3 + hm) * 128 * 512, 512,
                 m0, 8, smem, acc);

    const int tid = threadIdx.x, lane = tid & 31;
    const int wid = tid >> 5;
    const int wm = wid & 1, wn = wid >> 1;
    const int r0 = m0 + wm * 32 + (lane >> 2);
    const int c0 = wn * 32 + (lane & 3) * 2;       // 0..127: wn<2 -> w1, wn>=2 -> w2t
    float* Cb = (wn < 2) ? g_w1 : g_w2t;
    const int j0 = c0 & 63;
    const size_t base = (size_t)((b*4 + hm + 1) * Tv);
#pragma unroll
    for (int f = 0; f < 2; ++f)
#pragma unroll
        for (int n = 0; n < 4; ++n) {
            float* p0 = Cb + (base + r0 + f * 16) * 64 + j0 + n * 8;
            *(float2*)p0 = make_float2(acc[f][n][0], acc[f][n][1]);
            *(float2*)(p0 + 8 * 64) = make_float2(acc[f][n][2], acc[f][n][3]);
        }
}

// ================= SIMT fp32 64x64 GEMM tile (landmark q/k only) =================
__device__ __forceinline__ void gemm_tile_64(
    const float* __restrict__ A, int lda,
    const float* __restrict__ Bm, int ldb,
    float* __restrict__ C, int ldc,
    int Kd, int m0, int n0)
{
    __shared__ __align__(16) float As[16][68];
    __shared__ __align__(16) float Bs[16][68];
    const int tid = threadIdx.x;
    const int tx = tid & 15, ty = tid >> 4;
    const int lr = tid >> 2;
    const int lc = (tid & 3) << 2;
    float acc[4][4] = {};
    const float* Ap = A + (size_t)(m0 + lr)*lda + lc;
    const float* Bp = Bm + (size_t)(n0 + lr)*ldb + lc;
    for (int k0 = 0; k0 < Kd; k0 += 16) {
        float4 av = *(const float4*)(Ap + k0);
        float4 bv = *(const float4*)(Bp + k0);
        As[lc+0][lr]=av.x; As[lc+1][lr]=av.y; As[lc+2][lr]=av.z; As[lc+3][lr]=av.w;
        Bs[lc+0][lr]=bv.x; Bs[lc+1][lr]=bv.y; Bs[lc+2][lr]=bv.z; Bs[lc+3][lr]=bv.w;
        __syncthreads();
#pragma unroll
        for (int kk = 0; kk < 16; ++kk) {
            float4 a = *(const float4*)&As[kk][ty<<2];
            float4 b = *(const float4*)&Bs[kk][tx<<2];
            acc[0][0] += a.x*b.x; acc[0][1] += a.x*b.y; acc[0][2] += a.x*b.z; acc[0][3] += a.x*b.w;
            acc[1][0] += a.y*b.x; acc[1][1] += a.y*b.y; acc[1][2] += a.y*b.z; acc[1][3] += a.y*b.w;
            acc[2][0] += a.z*b.x; acc[2][1] += a.z*b.y; acc[2][2] += a.z*b.z; acc[2][3] += a.z*b.w;
            acc[3][0] += a.w*b.x; acc[3][1] += a.w*b.y; acc[3][2] += a.w*b.z; acc[3][3] += a.w*b.w;
        }
        __syncthreads();
    }
#pragma unroll
    for (int i = 0; i < 4; i++) {
        float4 o;
        o.x = acc[i][0]; o.y = acc[i][1]; o.z = acc[i][2]; o.w = acc[i][3];
        *(float4*)(C + (size_t)(m0 + (ty<<2) + i)*ldc + n0 + (tx<<2)) = o;
    }
}

// landmark q/k: C[128, 384] = g_xlm @ (wq rows 128..511)^T. grid (2, 6, 2).
__global__ void __launch_bounds__(256) lmgemm(const float* __restrict__ wq,
                                              const float* __restrict__ wk)
{
    const float* Bm = (blockIdx.z ? wk : wq) + 128 * 512;
    float* C = blockIdx.z ? g_klm : g_qlm;
    gemm_tile_64(g_xlm, 512, Bm, 512, C, 384, 512, blockIdx.x * 64, blockIdx.y * 64);
}

// gather landmark x rows (fp32). grid 128, 128 threads.
__global__ void gather_lm(const float4* __restrict__ x, const int* __restrict__ lmk)
{
    int bid = blockIdx.x;
    int b = bid >> 6, j = bid & 63;
    int tok = lmk[j];
    ((float4*)g_xlm)[bid * 128 + threadIdx.x] =
        x[(size_t)(b * Tv + tok) * 128 + threadIdx.x];
}

// ================= fp32 -> (hi,lo) bf16 splits =================
__global__ void split_x(const float4* __restrict__ x)
{
    size_t i = (size_t)blockIdx.x * 256 + threadIdx.x;
    float4 v = x[i];
    __nv_bfloat16 h0 = __float2bfloat16(v.x), h1 = __float2bfloat16(v.y);
    __nv_bfloat16 h2 = __float2bfloat16(v.z), h3 = __float2bfloat16(v.w);
    __nv_bfloat162 hh0 = __halves2bfloat162(h0, h1);
    __nv_bfloat162 hh1 = __halves2bfloat162(h2, h3);
    ((uint2*)g_xh)[i] = make_uint2(*(uint32_t*)&hh0, *(uint32_t*)&hh1);
    __nv_bfloat162 ll0 = __halves2bfloat162(
        __float2bfloat16(v.x - __bfloat162float(h0)),
        __float2bfloat16(v.y - __bfloat162float(h1)));
    __nv_bfloat162 ll1 = __halves2bfloat162(
        __float2bfloat16(v.z - __bfloat162float(h2)),
        __float2bfloat16(v.w - __bfloat162float(h3)));
    ((uint2*)g_xl)[i] = make_uint2(*(uint32_t*)&ll0, *(uint32_t*)&ll1);
}
// wv (slot 0) and wo (slot 1). grid 1024.
__global__ void split_wvo(const float2* __restrict__ wv, const float2* __restrict__ wo)
{
    int widx = blockIdx.x >> 9;
    size_t i = (size_t)(blockIdx.x & 511) * 256 + threadIdx.x;
    const float2* src = widx ? wo : wv;
    __nv_bfloat162* dh = (__nv_bfloat162*)g_wh + (size_t)widx * (NN/2);
    __nv_bfloat162* dl = (__nv_bfloat162*)g_wl + (size_t)widx * (NN/2);
    float2 v = src[i];
    __nv_bfloat16 h0 = __float2bfloat16(v.x);
    __nv_bfloat16 h1 = __float2bfloat16(v.y);
    dh[i] = __halves2bfloat162(h0, h1);
    dl[i] = __halves2bfloat162(__float2bfloat16(v.x - __bfloat162float(h0)),
                               __float2bfloat16(v.y - __bfloat162float(h1)));
}

// transposed splits of wq/wk: wT[e,c] = w[c,e]. grid (8, 8, 2).
__global__ void __launch_bounds__(256) transpose_qk(const float* __restrict__ wq,
                                                    const float* __restrict__ wk)
{
    __shared__ float sm[64][65];
    const float* src = blockIdx.z ? wk : wq;
    __nv_bfloat16* dh = blockIdx.z ? g_wkth : g_wqth;
    __nv_bfloat16* dl = blockIdx.z ? g_wktl : g_wqtl;
    const int c0 = blockIdx.x * 64, e0 = blockIdx.y * 64;
    const int t = threadIdx.x;
#pragma unroll
    for (int i = 0; i < 16; ++i) {
        int idx = i * 256 + t;
        int r = idx >> 6, e = idx & 63;
        sm[r][e] = src[(size_t)(c0 + r) * 512 + e0 + e];
    }
    __syncthreads();
#pragma unroll
    for (int i = 0; i < 16; ++i) {
        int idx = i * 256 + t;
        int er = idx >> 6, c = idx & 63;
        float v = sm[c][er];
        __nv_bfloat16 h = __float2bfloat16(v);
        size_t o = (size_t)(e0 + er) * 512 + c0 + c;
        dh[o] = h;
        dl[o] = __float2bfloat16(v - __bfloat162float(h));
    }
}

// ================= lam scalar =================
__global__ void lam_kernel(const float* __restrict__ lq1, const float* __restrict__ lk1,
                           const float* __restrict__ lq2, const float* __restrict__ lk2,
                           const int* __restrict__ lptr)
{
    __shared__ float r1[128], r2[128];
    int t = threadIdx.x;
    r1[t] = lq1[t]*lk1[t];
    r2[t] = lq2[t]*lk2[t];
    __syncthreads();
    for (int o = 64; o; o >>= 1) {
        if (t < o) { r1[t] += r1[t+o]; r2[t] += r2[t+o]; }
        __syncthreads();
    }
    if (t == 0) {
        float lam_init = 0.8f - 0.6f*expf(-0.3f*(float)lptr[0]);
        g_scal[0] = expf(r1[0]) - expf(r2[0]) + lam_init;
        g_scal[1] = 1.0f - lam_init;
    }
}

// ===== sq / sk from fp32 landmark q/k: normalize, scale, split. 768 warps. ========
__global__ void __launch_bounds__(256) sqsk_kernel(const float* __restrict__ m1,
                                                   const float* __restrict__ m2)
{
    int task = blockIdx.x * 8 + (threadIdx.x >> 5);
    int lane = threadIdx.x & 31;
    int which = task & 1;          // 0: sq (qlm, m1)   1: sk (klm, m2)
    int rest = task >> 1;
    int j  = rest & 63;
    int hm = (rest >> 6) % 3;
    int b  = rest / 192;

    const float* src = (which ? g_klm : g_qlm) + ((size_t)(b*64 + j) * 384 + hm * 128 + lane * 4);
    float4 v = *(const float4*)src;
    float ss = v.x*v.x + v.y*v.y + v.z*v.z + v.w*v.w;
#pragma unroll
    for (int o = 16; o; o >>= 1) ss += __shfl_xor_sync(0xffffffffu, ss, o);

    float scale = (which ? m2[(hm+1)*Lv + j] : m1[(hm+1)*Lv + j]) * rsqrtf(ss);
    __nv_bfloat16* dh = which ? g_skh : g_sqh;
    __nv_bfloat16* dl = which ? g_skl : g_sql;
    size_t d = ((size_t)(b*3 + hm)*Lv + j)*HDv + lane*4;
    float vals[4] = {v.x*scale, v.y*scale, v.z*scale, v.w*scale};
#pragma unroll
    for (int e = 0; e < 4; ++e) {
        __nv_bfloat16 h = __float2bfloat16(vals[e]);
        dh[d+e] = h;
        dl[d+e] = __float2bfloat16(vals[e] - __bfloat162float(h));
    }
}

// ================= symmetric mask -> per-row CSR =================
__global__ void mask_kernel(const int* __restrict__ rns)
{
    int warp = (blockIdx.x * blockDim.x + threadIdx.x) >> 5;
    int lane = threadIdx.x & 31;
    int b = warp >> 11, i = warp & (Tv-1);
    const int* row = rns + (size_t)warp * KIv;
    int j = row[lane];
    bool dup = false;
#pragma unroll
    for (int k2 = 0; k2 < 32; ++k2) {
        int jj = __shfl_sync(0xffffffffu, j, k2);
        if (k2 < lane && jj == j) dup = true;
    }
    bool mem = false;
    const int* rj = rns + (size_t)(b*Tv + j)*KIv;
#pragma unroll
    for (int m = 0; m < 32; ++m) if (rj[m] == i) mem = true;
    bool valid = (!dup) && mem;
    unsigned bal = __ballot_sync(0xffffffffu, valid);
    if (valid) {
        int pos = __popc(bal & ((1u << lane) - 1u));
        g_cols[(size_t)warp*KIv + pos] = j;
    }
    if (lane == 0) g_cnt[warp] = __popc(bal);
}

// ================= column partial sums of v (zero-nnz rows) =================
__global__ void colsumA()
{
    int g = blockIdx.x*256 + threadIdx.x;
    int chunk = g >> 10;
    int c = g & 1023;
    int b = c >> 9, col = c & 511;
    const float* p = g_v + (size_t)(b*Tv + chunk*256)*NXv + col;
    float s = 0.f;
    for (int t = 0; t < 256; ++t) s += p[(size_t)t*NXv];
    g_vpart[g] = s;
}

// ================= sparse attention: 2 rows per block ==============================
__global__ void __launch_bounds__(256) attn_rows(const float* __restrict__ rms_g, int r_base)
{
    const int half = threadIdx.x >> 7;
    const int t = threadIdx.x & 127;
    const int r = r_base + blockIdx.x * 2 + half;
    const int b = r >> 11;
    const int i = r & (Tv-1);
    __shared__ int   scols[2][KIv];
    __shared__ float sw[2][3][KIv];
    __shared__ float cc0[2][KIv], cc1[2][KIv];
    __shared__ float red[2][2][128];
    const int cnt = g_cnt[r];
    if (t < KIv && t < cnt) scols[half][t] = g_cols[(size_t)r*KIv + t];
    __syncthreads();
    const float lam = g_scal[0];
    const int wid = (threadIdx.x >> 5) & 3;
    const int lane = threadIdx.x & 31;

    for (int task = wid; task < 3*cnt; task += 4) {
        int hm = task % 3, j = task / 3, h = hm + 1;
        const float* w1p = g_w1  + ((size_t)((b*4+h)*Tv + i)              << 6);
        const float* w2p = g_w2t + ((size_t)((b*4+h)*Tv + scols[half][j]) << 6);
        float s = w1p[lane]*w2p[lane] + w1p[lane+32]*w2p[lane+32];
#pragma unroll
        for (int o = 16; o; o >>= 1) s += __shfl_xor_sync(0xffffffffu, s, o);
        if (lane == 0) sw[half][hm][j] = s;
    }
    __syncthreads();

    if (wid == 0 && cnt > 0) {
        float p[3];
#pragma unroll
        for (int hm = 0; hm < 3; ++hm) {
            float x = (lane < cnt) ? sw[half][hm][lane] : -INFINITY;
            float mx = x;
#pragma unroll
            for (int o = 16; o; o >>= 1) mx = fmaxf(mx, __shfl_xor_sync(0xffffffffu, mx, o));
            float e = (lane < cnt) ? expf(x - mx) : 0.f;
            float sm = e;
#pragma unroll
            for (int o = 16; o; o >>= 1) sm += __shfl_xor_sync(0xffffffffu, sm, o);
            p[hm] = e / sm;
        }
        if (lane < cnt) {
            cc0[half][lane] = (1.f - lam)*p[1] - lam*p[0];
            cc1[half][lane] = p[1] - p[0] + (1.f - 2.f*lam)*p[2];
        }
    }
    __syncthreads();

    float s0a = 0.f, s0b = 0.f, s1a = 0.f, s1b = 0.f;
    if (cnt > 0) {
        for (int j = 0; j < cnt; ++j) {
            const float* vp = g_v + ((size_t)(b*Tv + scols[half][j]) << 9);
            float w0 = cc0[half][j], w1 = cc1[half][j];
            s0a += w0 * vp[t];
            s0b += w0 * vp[t + 128];
            s1a += w1 * vp[t + 256];
            s1b += w1 * vp[t + 384];
        }
    } else {
        float u = (1.f - 2.f*lam) * (1.f/(float)Tv);
        float t0 = 0.f, t1 = 0.f, t2 = 0.f, t3 = 0.f;
#pragma unroll
        for (int ch = 0; ch < 8; ++ch) {
            const float* vp = g_vpart + ch*1024 + b*512;
            t0 += vp[t]; t1 += vp[t+128]; t2 += vp[t+256]; t3 += vp[t+384];
        }
        s0a = u * t0; s0b = u * t1; s1a = u * t2; s1b = u * t3;
    }

    red[half][0][t] = s0a*s0a + s0b*s0b;
    red[half][1][t] = s1a*s1a + s1b*s1b;
    __syncthreads();
#pragma unroll
    for (int o = 64; o; o >>= 1) {
        if (t < o) {
            red[half][0][t] += red[half][0][t+o];
            red[half][1][t] += red[half][1][t+o];
        }
        __syncthreads();
    }
    const float onem = g_scal[1];
    const float gA = rms_g[t], gB = rms_g[t + 128];
    float sc0 = rsqrtf(red[half][0][0]*(1.f/256.f) + 1e-5f) * onem;
    float sc1 = rsqrtf(red[half][1][0]*(1.f/256.f) + 1e-5f) * onem;
    float a0 = s0a * sc0 * gA, a1 = s0b * sc0 * gB;
    float a2 = s1a * sc1 * gA, a3 = s1b * sc1 * gB;
    size_t base = (size_t)r * NXv;
    float vals[4] = {a0, a1, a2, a3};
    int offs[4] = {t, t + 128, t + 256, t + 384};
#pragma unroll
    for (int e = 0; e < 4; ++e) {
        __nv_bfloat16 h = __float2bfloat16(vals[e]);
        g_ah[base + offs[e]] = h;
        g_al[base + offs[e]] = __float2bfloat16(vals[e] - __bfloat162float(h));
    }
}

// ================= launch (multi-stream fork/join, graph-capture safe) =============
extern "C" void kernel_launch(void* const* d_in, const int* in_sizes, int n_in,
                              void* d_out, int out_size)
{
    const float* x    = (const float*)d_in[0];
    const float* wq   = (const float*)d_in[1];
    const float* wk   = (const float*)d_in[2];
    const float* wv   = (const float*)d_in[3];
    const float* wo   = (const float*)d_in[4];
    const float* m1   = (const float*)d_in[5];
    const float* m2   = (const float*)d_in[6];
    const float* lq1  = (const float*)d_in[7];
    const float* lk1  = (const float*)d_in[8];
    const float* lq2  = (const float*)d_in[9];
    const float* lk2  = (const float*)d_in[10];
    const float* rmsg = (const float*)d_in[11];
    const int*   lp   = (const int*)d_in[12];
    const int*   rns  = (const int*)d_in[14];
    const int*   lmk  = (const int*)d_in[15];
    float* out = (float*)d_out;

    static cudaStream_t s1 = nullptr, s2 = nullptr;
    static cudaEvent_t e_fork = nullptr, e_tr = nullptr, e_mask = nullptr,
                       e_sx = nullptr, e_w12 = nullptr, e_a0 = nullptr, e_o0 = nullptr;
    static int inited = 0;
    if (!inited) {
        cudaStreamCreateWithFlags(&s1, cudaStreamNonBlocking);
        cudaStreamCreateWithFlags(&s2, cudaStreamNonBlocking);
        cudaEventCreateWithFlags(&e_fork, cudaEventDisableTiming);
        cudaEventCreateWithFlags(&e_tr,   cudaEventDisableTiming);
        cudaEventCreateWithFlags(&e_mask, cudaEventDisableTiming);
        cudaEventCreateWithFlags(&e_sx,   cudaEventDisableTiming);
        cudaEventCreateWithFlags(&e_w12,  cudaEventDisableTiming);
        cudaEventCreateWithFlags(&e_a0,   cudaEventDisableTiming);
        cudaEventCreateWithFlags(&e_o0,   cudaEventDisableTiming);
        cudaFuncSetAttribute(gemm_v,   cudaFuncAttributeMaxDynamicSharedMemorySize, GEMM_SMEM_TOTAL);
        cudaFuncSetAttribute(gemm_out, cudaFuncAttributeMaxDynamicSharedMemorySize, GEMM_SMEM_TOTAL);
        cudaFuncSetAttribute(mgemm,    cudaFuncAttributeMaxDynamicSharedMemorySize, GEMM_SMEM_TOTAL);
        cudaFuncSetAttribute(wgemm,    cudaFuncAttributeMaxDynamicSharedMemorySize, GEMM_SMEM_TOTAL);
        inited = 1;
    }

    cudaEventRecord(e_fork, 0);

    // s1: landmark chain (input-only start): gather -> SIMT lm-gemm -> sqsk
    cudaStreamWaitEvent(s1, e_fork, 0);
    gather_lm<<<128, 128, 0, s1>>>((const float4*)x, lmk);
    lmgemm<<<dim3(2, 6, 2), 256, 0, s1>>>(wq, wk);
    sqsk_kernel<<<96, 256, 0, s1>>>(m1, m2);

    // s2: transposed weight splits + lam + mask (input-only)
    cudaStreamWaitEvent(s2, e_fork, 0);
    transpose_qk<<<dim3(8, 8, 2), 256, 0, s2>>>(wq, wk);
    cudaEventRecord(e_tr, s2);
    lam_kernel<<<1, 128, 0, s2>>>(lq1, lk1, lq2, lk2, lp);
    mask_kernel<<<Bv*Tv*32/256, 256, 0, s2>>>(rns);
    cudaEventRecord(e_mask, s2);

    // s1 continues: M-gemm (needs sqsk + transposed weights)
    cudaStreamWaitEvent(s1, e_tr, 0);
    mgemm<<<dim3(4, Bv*3, 2), 256, GEMM_SMEM_TOTAL, s1>>>();

    // main: x split + wv/wo split -> v projection
    split_x<<<2048, 256>>>((const float4*)x);
    cudaEventRecord(e_sx, 0);
    split_wvo<<<1024, 256>>>((const float2*)wv, (const float2*)wo);

    // s1: w-gemm (needs x splits + M splits)
    cudaStreamWaitEvent(s1, e_sx, 0);
    wgemm<<<dim3(Tv/64, 3, Bv), 256, GEMM_SMEM_TOTAL, s1>>>();
    cudaEventRecord(e_w12, s1);

    gemm_v<<<dim3(Bv*Tv/64, 4), 256, GEMM_SMEM_TOTAL>>>();
    colsumA<<<32, 256>>>();

    // join + pipelined attn/out by batch
    cudaStreamWaitEvent(0, e_w12, 0);
    cudaStreamWaitEvent(0, e_mask, 0);
    attn_rows<<<Tv/2, 256>>>(rmsg, 0);
    cudaEventRecord(e_a0, 0);

    cudaStreamWaitEvent(s2, e_a0, 0);
    gemm_out<<<dim3(Tv/64, 4), 256, GEMM_SMEM_TOTAL, s2>>>(out, 0);
    cudaEventRecord(e_o0, s2);

    attn_rows<<<Tv/2, 256>>>(rmsg, Bv*Tv/2);
    gemm_out<<<dim3(Tv/64, 4), 256, GEMM_SMEM_TOTAL>>>(out, Bv*Tv/2);
    cudaStreamWaitEvent(0, e_o0, 0);
}